// round 1
// baseline (speedup 1.0000x reference)
#include <cuda_runtime.h>
#include <cuda_bf16.h>
#include <cstdint>
#include <cstdio>

// Problem constants
#define PP 16
#define EE 512
#define HH 512
#define NN 8192

// Tiling
#define BM 128          // entity rows per block
#define BK 32           // K chunk
#define NC 128          // output-column chunk per pass
#define BKP 36          // padded A row stride (floats): bank-conflict-free frags
#define NCP 136         // padded B row stride (floats): bank-conflict-free frags
#define KCH (512 / BK)  // 16 K-chunks per pass
#define THREADS 256

// Scratch for h0 = relu(x @ W0 + b0): [P][N][H] fp32. Per-block 256KB slice is
// written then immediately re-read by the same block -> stays in L2.
__device__ float g_h0[(size_t)PP * NN * HH];

__device__ __forceinline__ float tf32r(float x) {
    uint32_t u;
    asm("cvt.rna.tf32.f32 %0, %1;" : "=r"(u) : "f"(x));
    return __uint_as_float(u);
}

__device__ __forceinline__ float4 tf4(float4 v) {
    float4 r;
    r.x = tf32r(v.x); r.y = tf32r(v.y); r.z = tf32r(v.z); r.w = tf32r(v.w);
    return r;
}

__device__ __forceinline__ void mma8(float c[4], const uint32_t a[4],
                                     uint32_t b0, uint32_t b1) {
    asm volatile(
        "mma.sync.aligned.m16n8k8.row.col.f32.tf32.tf32.f32 "
        "{%0,%1,%2,%3}, {%4,%5,%6,%7}, {%8,%9}, {%0,%1,%2,%3};\n"
        : "+f"(c[0]), "+f"(c[1]), "+f"(c[2]), "+f"(c[3])
        : "r"(a[0]), "r"(a[1]), "r"(a[2]), "r"(a[3]), "r"(b0), "r"(b1));
}

// Load one K-chunk (A: [BM x BK], B: [BK x NC]) from global into registers.
__device__ __forceinline__ void load_chunk(const float* __restrict__ Ag,
                                           const float* __restrict__ Bg,
                                           int kc, int tid,
                                           float4 ra[4], float4 rb[4]) {
#pragma unroll
    for (int j = 0; j < 4; j++) {
        int idx = tid + j * THREADS;
        // A: 128 rows x 8 float4; coalesced (8 consecutive lanes cover a 128B row-chunk)
        ra[j] = *(const float4*)(Ag + (size_t)(idx >> 3) * 512 + kc * BK + ((idx & 7) << 2));
        // B: 32 rows x 32 float4; fully coalesced rows
        rb[j] = *(const float4*)(Bg + (size_t)(kc * BK + (idx >> 5)) * 512 + ((idx & 31) << 2));
    }
}

// Store a prefetched chunk into SMEM (with round-to-nearest tf32 conversion).
__device__ __forceinline__ void store_chunk(float* __restrict__ sA,
                                            float* __restrict__ sB,
                                            int buf, int tid,
                                            const float4 ra[4], const float4 rb[4]) {
#pragma unroll
    for (int j = 0; j < 4; j++) {
        int idx = tid + j * THREADS;
        // A stored row-major [m][k] with pad 36 -> STS.128, 4-phase minimum
        *(float4*)(sA + buf * (BM * BKP) + (idx >> 3) * BKP + ((idx & 7) << 2)) = tf4(ra[j]);
        // B stored row-major [k][n] with pad 136 -> conflict-free
        *(float4*)(sB + buf * (BK * NCP) + (idx >> 5) * NCP + ((idx & 31) << 2)) = tf4(rb[j]);
    }
}

__device__ __forceinline__ void compute_chunk(const float* __restrict__ sA,
                                              const float* __restrict__ sB,
                                              int buf, int wm, int wn, int qid, int qt,
                                              float acc[2][8][4]) {
    const float* cA = sA + buf * (BM * BKP);
    const float* cB = sB + buf * (BK * NCP);
#pragma unroll
    for (int kk = 0; kk < BK; kk += 8) {
        uint32_t af[2][4];
#pragma unroll
        for (int mt = 0; mt < 2; mt++) {
            int m = wm * 32 + mt * 16 + qid;
            // m16n8k8 tf32 A frag: a0 (qid, qt), a1 (qid+8, qt), a2 (qid, qt+4), a3 (qid+8, qt+4)
            af[mt][0] = __float_as_uint(cA[m * BKP + kk + qt]);
            af[mt][1] = __float_as_uint(cA[(m + 8) * BKP + kk + qt]);
            af[mt][2] = __float_as_uint(cA[m * BKP + kk + 4 + qt]);
            af[mt][3] = __float_as_uint(cA[(m + 8) * BKP + kk + 4 + qt]);
        }
#pragma unroll
        for (int nt = 0; nt < 8; nt++) {
            int n = wn * 64 + nt * 8 + qid;
            // B frag: b0 (k=qt, n=qid), b1 (k=qt+4, n=qid)
            uint32_t b0 = __float_as_uint(cB[(kk + qt) * NCP + n]);
            uint32_t b1 = __float_as_uint(cB[(kk + 4 + qt) * NCP + n]);
            mma8(acc[0][nt], af[0], b0, b1);
            mma8(acc[1][nt], af[1], b0, b1);
        }
    }
}

// One GEMM pass: acc[BM x NC] = A[BM x 512] * B[512 x NC]  (tf32 mma, fp32 accum)
__device__ __forceinline__ void run_pass(const float* __restrict__ Ag,
                                         const float* __restrict__ Bg,
                                         float* __restrict__ sA, float* __restrict__ sB,
                                         int tid, int wm, int wn, int qid, int qt,
                                         float acc[2][8][4]) {
#pragma unroll
    for (int mt = 0; mt < 2; mt++)
#pragma unroll
        for (int nt = 0; nt < 8; nt++)
#pragma unroll
            for (int c = 0; c < 4; c++) acc[mt][nt][c] = 0.f;

    float4 ra[4], rb[4];
    load_chunk(Ag, Bg, 0, tid, ra, rb);
    store_chunk(sA, sB, 0, tid, ra, rb);
    __syncthreads();

    int buf = 0;
    for (int kc = 0; kc < KCH; kc++) {
        if (kc + 1 < KCH) load_chunk(Ag, Bg, kc + 1, tid, ra, rb);  // overlap w/ mma
        compute_chunk(sA, sB, buf, wm, wn, qid, qt, acc);
        if (kc + 1 < KCH) {
            __syncthreads();
            store_chunk(sA, sB, buf ^ 1, tid, ra, rb);
            __syncthreads();
            buf ^= 1;
        }
    }
}

__global__ void __launch_bounds__(THREADS, 1)
mlp_kernel(const float* __restrict__ x, const float* __restrict__ W0,
           const float* __restrict__ b0, const float* __restrict__ W1,
           const float* __restrict__ b1, const float* __restrict__ W2,
           const float* __restrict__ b2, float* __restrict__ out) {
    extern __shared__ float smem[];
    float* sA = smem;                       // 2 * 128 * 36 floats
    float* sB = smem + 2 * BM * BKP;        // 2 * 32 * 136 floats
    float* sLog = sB + 2 * BK * NCP;        // 128 floats

    const int tid = threadIdx.x;
    const int warp = tid >> 5, lane = tid & 31;
    const int wm = warp >> 1, wn = warp & 1;   // 4 x 2 warp grid
    const int qid = lane >> 2, qt = lane & 3;
    const int p = blockIdx.y;
    const int gm0 = blockIdx.x * BM;

    const float* Ax = x + (size_t)gm0 * EE;
    float* hbase = g_h0 + ((size_t)p * NN + gm0) * HH;

    // ---------------- Layer 0: h0 = relu(x @ W0[p] + b0[p]) ----------------
    for (int pass = 0; pass < 4; pass++) {
        const int n0 = pass * NC;
        float acc[2][8][4];
        run_pass(Ax, W0 + (size_t)p * EE * HH + n0, sA, sB, tid, wm, wn, qid, qt, acc);

        const float* bptr = b0 + p * HH + n0;
#pragma unroll
        for (int nt = 0; nt < 8; nt++) {
            int col = wn * 64 + nt * 8 + qt * 2;
            float2 bb = *(const float2*)(bptr + col);
#pragma unroll
            for (int mt = 0; mt < 2; mt++) {
                int row = wm * 32 + mt * 16 + qid;
                float v0 = fmaxf(acc[mt][nt][0] + bb.x, 0.f);
                float v1 = fmaxf(acc[mt][nt][1] + bb.y, 0.f);
                float v2 = fmaxf(acc[mt][nt][2] + bb.x, 0.f);
                float v3 = fmaxf(acc[mt][nt][3] + bb.y, 0.f);
                *(float2*)(hbase + (size_t)row * HH + n0 + col) = make_float2(v0, v1);
                *(float2*)(hbase + (size_t)(row + 8) * HH + n0 + col) = make_float2(v2, v3);
            }
        }
    }
    __syncthreads();  // h0 writes visible block-wide before layer-1 reads

    if (tid < BM) sLog[tid] = 0.f;  // ordered before atomics by run_pass's internal sync

    // ------- Layer 1 + 2 fused: logit[n] = sum_h relu(h1[n,h]) * W2[p,h] -------
    float lpart[4] = {0.f, 0.f, 0.f, 0.f};
    for (int pass = 0; pass < 4; pass++) {
        const int n0 = pass * NC;
        float acc[2][8][4];
        run_pass(hbase, W1 + (size_t)p * HH * HH + n0, sA, sB, tid, wm, wn, qid, qt, acc);

        const float* bptr = b1 + p * HH + n0;
        const float* wptr = W2 + p * HH + n0;
#pragma unroll
        for (int nt = 0; nt < 8; nt++) {
            int col = wn * 64 + nt * 8 + qt * 2;
            float2 bb = *(const float2*)(bptr + col);
            float2 ww = *(const float2*)(wptr + col);
#pragma unroll
            for (int mt = 0; mt < 2; mt++) {
                float v0 = fmaxf(acc[mt][nt][0] + bb.x, 0.f);
                float v1 = fmaxf(acc[mt][nt][1] + bb.y, 0.f);
                float v2 = fmaxf(acc[mt][nt][2] + bb.x, 0.f);
                float v3 = fmaxf(acc[mt][nt][3] + bb.y, 0.f);
                lpart[2 * mt]     += v0 * ww.x + v1 * ww.y;
                lpart[2 * mt + 1] += v2 * ww.x + v3 * ww.y;
            }
        }
    }

    // Reduce partial dot-products: quad (lanes differing in qt), then smem atomics
#pragma unroll
    for (int i = 0; i < 4; i++) {
        float v = lpart[i];
        v += __shfl_xor_sync(0xffffffffu, v, 1);
        v += __shfl_xor_sync(0xffffffffu, v, 2);
        if (qt == 0) {
            int row = wm * 32 + (i >> 1) * 16 + ((i & 1) ? 8 : 0) + qid;
            atomicAdd(&sLog[row], v);
        }
    }
    __syncthreads();

    if (tid < BM) {
        float logit = sLog[tid] + b2[p];
        out[(size_t)(gm0 + tid) * PP + p] = 1.f / (1.f + expf(-logit));
    }
}

extern "C" void kernel_launch(void* const* d_in, const int* in_sizes, int n_in,
                              void* d_out, int out_size) {
    const float* x  = (const float*)d_in[0];
    const float* W0 = (const float*)d_in[1];
    const float* b0 = (const float*)d_in[2];
    const float* W1 = (const float*)d_in[3];
    const float* b1 = (const float*)d_in[4];
    const float* W2 = (const float*)d_in[5];
    const float* b2 = (const float*)d_in[6];
    float* out = (float*)d_out;

    const int smem_bytes = (2 * BM * BKP + 2 * BK * NCP + BM) * (int)sizeof(float);
    cudaFuncSetAttribute(mlp_kernel, cudaFuncAttributeMaxDynamicSharedMemorySize, smem_bytes);

    dim3 grid(NN / BM, PP);
    mlp_kernel<<<grid, THREADS, smem_bytes>>>(x, W0, b0, W1, b1, W2, b2, out);
}

// round 5
// speedup vs baseline: 1.3019x; 1.3019x over previous
#include <cuda_runtime.h>
#include <cstdint>

// Problem constants
#define PP 16
#define EE 512
#define HH 512
#define NN 8192

// Tiling: block tile 128x256, 8 warps as 2x4 grid, warp tile 64x64
#define BM 128
#define BN 256
#define BK 32
#define BKP 36          // padded A row stride (floats)
#define BNP 264         // padded B row stride (floats)
#define STAGES 3
#define KCH 16          // 512 / BK
#define THREADS 256

#define ASZ (BM * BKP)  // floats per A stage (4608)
#define BSZ (BK * BNP)  // floats per B stage (8448)

// Device scratch, declared as float4 so the base address is 16-byte aligned
// (required by cp.async 16B and float4 accesses).
__device__ float4 g_h0[(size_t)PP * NN * HH / 4];   // layer-0 activations (tf32 values)
__device__ float4 g_xt[(size_t)NN * EE / 4];        // tf32-rounded x
__device__ float4 g_w0t[(size_t)PP * EE * HH / 4];  // tf32-rounded W0
__device__ float4 g_w1t[(size_t)PP * HH * HH / 4];  // tf32-rounded W1

__device__ __forceinline__ float tf32r(float x) {
    uint32_t u;
    asm("cvt.rna.tf32.f32 %0, %1;" : "=r"(u) : "f"(x));
    return __uint_as_float(u);
}

// Pre-round x, W0, W1 to tf32 (RNA). All three arrays are exactly
// NN*EE == PP*EE*HH == 4194304 floats == 1048576 float4.
__global__ void cvt_all_kernel(const float4* __restrict__ x,
                               const float4* __restrict__ W0,
                               const float4* __restrict__ W1) {
    int j = blockIdx.x * blockDim.x + threadIdx.x;
    const int n4 = (NN * EE) / 4;
    if (j >= n4) return;
    float4 v;
    v = x[j];
    v.x = tf32r(v.x); v.y = tf32r(v.y); v.z = tf32r(v.z); v.w = tf32r(v.w);
    g_xt[j] = v;
    v = W0[j];
    v.x = tf32r(v.x); v.y = tf32r(v.y); v.z = tf32r(v.z); v.w = tf32r(v.w);
    g_w0t[j] = v;
    v = W1[j];
    v.x = tf32r(v.x); v.y = tf32r(v.y); v.z = tf32r(v.z); v.w = tf32r(v.w);
    g_w1t[j] = v;
}

__device__ __forceinline__ void mma8(float c[4], const uint32_t a[4],
                                     uint32_t b0, uint32_t b1) {
    asm volatile(
        "mma.sync.aligned.m16n8k8.row.col.f32.tf32.tf32.f32 "
        "{%0,%1,%2,%3}, {%4,%5,%6,%7}, {%8,%9}, {%0,%1,%2,%3};\n"
        : "+f"(c[0]), "+f"(c[1]), "+f"(c[2]), "+f"(c[3])
        : "r"(a[0]), "r"(a[1]), "r"(a[2]), "r"(a[3]), "r"(b0), "r"(b1));
}

// Issue cp.async for one K-chunk: A [BM x BK] + B [BK x BN] into stage s.
__device__ __forceinline__ void issue_chunk(const float* __restrict__ Ag,
                                            const float* __restrict__ Bg,
                                            int kc, int stage, int tid,
                                            uint32_t sAu, uint32_t sBu) {
#pragma unroll
    for (int j = 0; j < 4; j++) {             // A: 128x32 floats, 4 x cp.async.16/thread
        int idx = tid + j * THREADS;
        int m = idx >> 3, c = (idx & 7) << 2;
        uint32_t dst = sAu + ((uint32_t)(stage * ASZ + m * BKP + c) << 2);
        const float* src = Ag + (size_t)m * 512 + kc * BK + c;
        asm volatile("cp.async.cg.shared.global [%0], [%1], 16;\n" ::"r"(dst), "l"(src));
    }
#pragma unroll
    for (int j = 0; j < 8; j++) {             // B: 32x256 floats, 8 x cp.async.16/thread
        int idx = tid + j * THREADS;
        int k = idx >> 6, n = (idx & 63) << 2;
        uint32_t dst = sBu + ((uint32_t)(stage * BSZ + k * BNP + n) << 2);
        const float* src = Bg + (size_t)(kc * BK + k) * 512 + n;
        asm volatile("cp.async.cg.shared.global [%0], [%1], 16;\n" ::"r"(dst), "l"(src));
    }
    asm volatile("cp.async.commit_group;\n");
}

// MMA over one staged K-chunk. A frags via ldmatrix.x4 (tf32-as-b16 view),
// B frags via conflict-free scalar LDS.
__device__ __forceinline__ void compute_chunk(const float* __restrict__ sB,
                                              uint32_t aAddr0, int stage,
                                              int wn, int qid, int qt,
                                              float acc[4][8][4]) {
    const float* cB = sB + stage * BSZ;
    uint32_t aBase = aAddr0 + (uint32_t)stage * (ASZ * 4);
#pragma unroll
    for (int kk = 0; kk < BK; kk += 8) {
        uint32_t af[4][4];
#pragma unroll
        for (int mt = 0; mt < 4; mt++) {
            uint32_t addr = aBase + mt * (16 * BKP * 4) + kk * 4;
            asm volatile(
                "ldmatrix.sync.aligned.m8n8.x4.shared.b16 {%0,%1,%2,%3}, [%4];"
                : "=r"(af[mt][0]), "=r"(af[mt][1]), "=r"(af[mt][2]), "=r"(af[mt][3])
                : "r"(addr));
        }
#pragma unroll
        for (int nt = 0; nt < 8; nt++) {
            int n = wn * 64 + nt * 8 + qid;
            uint32_t b0 = __float_as_uint(cB[(kk + qt) * BNP + n]);
            uint32_t b1 = __float_as_uint(cB[(kk + 4 + qt) * BNP + n]);
#pragma unroll
            for (int mt = 0; mt < 4; mt++) mma8(acc[mt][nt], af[mt], b0, b1);
        }
    }
}

// One GEMM pass: acc[128x256] = A[128x512] * B[512x256], tf32 mma / fp32 accum.
__device__ __forceinline__ void gemm_pass(const float* __restrict__ Ag,
                                          const float* __restrict__ Bg,
                                          const float* __restrict__ sB,
                                          uint32_t sAu, uint32_t sBu, uint32_t aAddr0,
                                          int tid, int wn, int qid, int qt,
                                          float acc[4][8][4]) {
#pragma unroll
    for (int mt = 0; mt < 4; mt++)
#pragma unroll
        for (int nt = 0; nt < 8; nt++)
#pragma unroll
            for (int c = 0; c < 4; c++) acc[mt][nt][c] = 0.f;

    __syncthreads();  // prior pass/users fully done with all stages
    issue_chunk(Ag, Bg, 0, 0, tid, sAu, sBu);
    issue_chunk(Ag, Bg, 1, 1, tid, sAu, sBu);

    int stage = 0;  // stage of chunk kc == kc % STAGES
    for (int kc = 0; kc < KCH; kc++) {
        if (kc + 1 < KCH) {
            asm volatile("cp.async.wait_group 1;\n" ::);
        } else {
            asm volatile("cp.async.wait_group 0;\n" ::);
        }
        __syncthreads();  // chunk kc resident; all warps done with stage being refilled
        if (kc + 2 < KCH) {
            // FIX: stage of chunk kc+2 is (stage + 2) mod STAGES (was a broken
            // pseudo-modulo that produced stage indices up to 9 -> smem OOB).
            int s2 = stage + 2;
            if (s2 >= STAGES) s2 -= STAGES;
            issue_chunk(Ag, Bg, kc + 2, s2, tid, sAu, sBu);
        }
        compute_chunk(sB, aAddr0, stage, wn, qid, qt, acc);
        stage = (stage == STAGES - 1) ? 0 : stage + 1;
    }
}

__global__ void __launch_bounds__(THREADS, 1)
mlp_kernel(const float* __restrict__ b0, const float* __restrict__ b1,
           const float* __restrict__ W2, const float* __restrict__ b2,
           float* __restrict__ out) {
    extern __shared__ float smem[];
    float* sB = smem + STAGES * ASZ;
    float* sLog = smem + STAGES * ASZ + STAGES * BSZ;  // 128 floats

    uint32_t smem_u32;
    asm("{ .reg .u64 t; cvta.to.shared.u64 t, %1; cvt.u32.u64 %0, t; }"
        : "=r"(smem_u32) : "l"(smem));
    const uint32_t sAu = smem_u32;
    const uint32_t sBu = smem_u32 + (uint32_t)(STAGES * ASZ) * 4;

    const int tid = threadIdx.x;
    const int warp = tid >> 5, lane = tid & 31;
    const int wm = warp >> 2, wn = warp & 3;  // 2 x 4 warp grid
    const int qid = lane >> 2, qt = lane & 3;
    const int p = blockIdx.y;
    const int gm0 = blockIdx.x * BM;

    // Per-lane ldmatrix base address (mt=0, kk=0, stage=0)
    const uint32_t aAddr0 =
        sAu + (uint32_t)(((wm * 64 + (lane & 15)) * BKP + ((lane & 16) ? 4 : 0)) << 2);

    const float* Ax = (const float*)g_xt + (size_t)gm0 * EE;
    float* hbase = (float*)g_h0 + ((size_t)p * NN + gm0) * HH;

    float acc[4][8][4];

    // ---------------- Layer 0: h0 = tf32(relu(x @ W0[p] + b0[p])) ----------------
    for (int pass = 0; pass < 2; pass++) {
        const int n0 = pass * BN;
        gemm_pass(Ax, (const float*)g_w0t + (size_t)p * EE * HH + n0, sB, sAu, sBu,
                  aAddr0, tid, wn, qid, qt, acc);

        const float* bptr = b0 + p * HH + n0;
#pragma unroll
        for (int nt = 0; nt < 8; nt++) {
            int col = wn * 64 + nt * 8 + qt * 2;
            float2 bb = *(const float2*)(bptr + col);
#pragma unroll
            for (int mt = 0; mt < 4; mt++) {
                int row = wm * 64 + mt * 16 + qid;
                float2 o0 = make_float2(tf32r(fmaxf(acc[mt][nt][0] + bb.x, 0.f)),
                                        tf32r(fmaxf(acc[mt][nt][1] + bb.y, 0.f)));
                float2 o1 = make_float2(tf32r(fmaxf(acc[mt][nt][2] + bb.x, 0.f)),
                                        tf32r(fmaxf(acc[mt][nt][3] + bb.y, 0.f)));
                *(float2*)(hbase + (size_t)row * HH + n0 + col) = o0;
                *(float2*)(hbase + (size_t)(row + 8) * HH + n0 + col) = o1;
            }
        }
    }

    __threadfence();   // h0 globally visible before cp.async reads it
    __syncthreads();
    if (tid < BM) sLog[tid] = 0.f;  // ordered before atomics by gemm_pass's syncs

    // ------- Layer 1 + 2 fused: logit[n] = sum_h relu(h1[n,h]) * W2[p,h] -------
    float lpart[8];
#pragma unroll
    for (int i = 0; i < 8; i++) lpart[i] = 0.f;

    for (int pass = 0; pass < 2; pass++) {
        const int n0 = pass * BN;
        gemm_pass(hbase, (const float*)g_w1t + (size_t)p * HH * HH + n0, sB, sAu, sBu,
                  aAddr0, tid, wn, qid, qt, acc);

        const float* bptr = b1 + p * HH + n0;
        const float* wptr = W2 + p * HH + n0;
#pragma unroll
        for (int nt = 0; nt < 8; nt++) {
            int col = wn * 64 + nt * 8 + qt * 2;
            float2 bb = *(const float2*)(bptr + col);
            float2 ww = *(const float2*)(wptr + col);
#pragma unroll
            for (int mt = 0; mt < 4; mt++) {
                float v0 = fmaxf(acc[mt][nt][0] + bb.x, 0.f);
                float v1 = fmaxf(acc[mt][nt][1] + bb.y, 0.f);
                float v2 = fmaxf(acc[mt][nt][2] + bb.x, 0.f);
                float v3 = fmaxf(acc[mt][nt][3] + bb.y, 0.f);
                lpart[2 * mt]     += v0 * ww.x + v1 * ww.y;  // row qid
                lpart[2 * mt + 1] += v2 * ww.x + v3 * ww.y;  // row qid+8
            }
        }
    }

    // Reduce across qt lanes (quad), then smem atomics across warps/nt
#pragma unroll
    for (int i = 0; i < 8; i++) {
        float v = lpart[i];
        v += __shfl_xor_sync(0xffffffffu, v, 1);
        v += __shfl_xor_sync(0xffffffffu, v, 2);
        if (qt == 0) {
            int row = wm * 64 + (i >> 1) * 16 + ((i & 1) ? 8 : 0) + qid;
            atomicAdd(&sLog[row], v);
        }
    }
    __syncthreads();

    if (tid < BM) {
        float logit = sLog[tid] + b2[p];
        out[(size_t)(gm0 + tid) * PP + p] = 1.f / (1.f + expf(-logit));
    }
}

extern "C" void kernel_launch(void* const* d_in, const int* in_sizes, int n_in,
                              void* d_out, int out_size) {
    const float* x  = (const float*)d_in[0];
    const float* W0 = (const float*)d_in[1];
    const float* b0 = (const float*)d_in[2];
    const float* W1 = (const float*)d_in[3];
    const float* b1 = (const float*)d_in[4];
    const float* W2 = (const float*)d_in[5];
    const float* b2 = (const float*)d_in[6];
    float* out = (float*)d_out;

    // Pre-round x/W0/W1 to tf32 (RNA) once per launch (~12us)
    const int n4 = (NN * EE) / 4;           // 1048576
    cvt_all_kernel<<<n4 / 512, 512>>>((const float4*)x, (const float4*)W0,
                                      (const float4*)W1);

    const int smem_bytes = (STAGES * ASZ + STAGES * BSZ + BM) * (int)sizeof(float);
    cudaFuncSetAttribute(mlp_kernel, cudaFuncAttributeMaxDynamicSharedMemorySize,
                         smem_bytes);

    dim3 grid(NN / BM, PP);
    mlp_kernel<<<grid, THREADS, smem_bytes>>>(b0, b1, W2, b2, out);
}

// round 9
// speedup vs baseline: 2.0030x; 1.5386x over previous
#include <cuda_runtime.h>
#include <cuda_fp16.h>
#include <cstdint>

// Problem constants
#define PP 16
#define EE 512
#define HH 512
#define NN 8192

// Tiling: block tile 128x256, 8 warps (2x4), warp tile 64x64, fp16 K-chunk = 64
#define BM 128
#define BN 256
#define BK 64           // half elements per chunk (= 128B per row)
#define NCHUNK 8        // 512 / 64
#define STAGES 3
#define THREADS 256

#define ROWB 144                 // padded row stride in bytes (128B data + 16B pad)
#define ASTG (128 * ROWB)        // 18432 B per A stage
#define BSTG (256 * ROWB)        // 36864 B per B stage
#define OFF_B (STAGES * ASTG)    // B stages after A stages
#define OFF_LOG (STAGES * ASTG + STAGES * BSTG)   // 165888
#define SMEM_DYN (OFF_LOG + 512 + 16)

// Device scratch (uint4 => 16B aligned). All values stored as fp16 (RN).
__device__ uint4 g_xh[(size_t)NN * EE / 8];         // x          [N][E]   half
__device__ uint4 g_w0h[(size_t)PP * EE * HH / 8];   // W0^T       [P][H][E] half (K-major)
__device__ uint4 g_w1h[(size_t)PP * HH * HH / 8];   // W1^T       [P][Ho][Hi] half
__device__ uint4 g_h0h[(size_t)PP * NN * HH / 8];   // h0         [P][N][H] half

__device__ __forceinline__ uint32_t h2u(__half2 v) {
    uint32_t u;
    memcpy(&u, &v, 4);
    return u;
}

// ---------------- Prologue kernels ----------------

// x fp32 -> fp16, 8 elements/thread
__global__ void cvt_x_kernel(const float4* __restrict__ x) {
    int j = blockIdx.x * blockDim.x + threadIdx.x;
    if (j >= NN * EE / 8) return;
    float4 a = x[2 * j], b = x[2 * j + 1];
    uint4 o;
    o.x = h2u(__floats2half2_rn(a.x, a.y));
    o.y = h2u(__floats2half2_rn(a.z, a.w));
    o.z = h2u(__floats2half2_rn(b.x, b.y));
    o.w = h2u(__floats2half2_rn(b.z, b.w));
    g_xh[j] = o;
}

// Transpose + fp16-convert W0 [P,E,H]->[P,H,E] and W1 [P,H,H]->[P,Ho,Hi]
__global__ void transpose_w_kernel(const float* __restrict__ W0,
                                   const float* __restrict__ W1) {
    __shared__ float t[32][33];
    const int z = blockIdx.z;  // 0..15: W0 p=z ; 16..31: W1 p=z-16
    const float* src = (z < 16) ? W0 + (size_t)z * EE * HH
                                : W1 + (size_t)(z - 16) * HH * HH;
    __half* dst = (z < 16) ? (__half*)g_w0h + (size_t)z * EE * HH
                           : (__half*)g_w1h + (size_t)(z - 16) * HH * HH;
    const int c0 = blockIdx.x * 32;  // src col (output-neuron n) base
    const int r0 = blockIdx.y * 32;  // src row (input-dim k) base
    const int tx = threadIdx.x, ty = threadIdx.y;
#pragma unroll
    for (int i = ty; i < 32; i += 8)
        t[i][tx] = src[(size_t)(r0 + i) * 512 + c0 + tx];
    __syncthreads();
#pragma unroll
    for (int i = ty; i < 32; i += 8)
        dst[(size_t)(c0 + i) * 512 + r0 + tx] = __float2half_rn(t[tx][i]);
}

// ---------------- Main kernel ----------------

__device__ __forceinline__ void mma16(float c[4], const uint32_t a[4],
                                      uint32_t b0, uint32_t b1) {
    asm volatile(
        "mma.sync.aligned.m16n8k16.row.col.f32.f16.f16.f32 "
        "{%0,%1,%2,%3}, {%4,%5,%6,%7}, {%8,%9}, {%0,%1,%2,%3};\n"
        : "+f"(c[0]), "+f"(c[1]), "+f"(c[2]), "+f"(c[3])
        : "r"(a[0]), "r"(a[1]), "r"(a[2]), "r"(a[3]), "r"(b0), "r"(b1));
}

#define LDSM_X4(r, addr)                                                     \
    asm volatile("ldmatrix.sync.aligned.m8n8.x4.shared.b16 {%0,%1,%2,%3}, [%4];" \
                 : "=r"((r)[0]), "=r"((r)[1]), "=r"((r)[2]), "=r"((r)[3])    \
                 : "r"(addr))

// cp.async one K-chunk: A [128 rows x 128B] + B [256 rows x 128B] into a stage.
__device__ __forceinline__ void issue_chunk(const __half* __restrict__ Ag,
                                            const __half* __restrict__ Bg,
                                            int kc, int stage, int tid,
                                            uint32_t sAu, uint32_t sBu) {
    const uint32_t aB = sAu + stage * ASTG;
    const uint32_t bB = sBu + stage * BSTG;
#pragma unroll
    for (int j = 0; j < 4; j++) {             // A: 1024 x 16B
        int idx = tid + j * THREADS;
        int r = idx >> 3, c = idx & 7;
        uint32_t dst = aB + (uint32_t)(r * ROWB + c * 16);
        const __half* src = Ag + (size_t)r * 512 + kc * BK + c * 8;
        asm volatile("cp.async.cg.shared.global [%0], [%1], 16;\n" ::"r"(dst), "l"(src));
    }
#pragma unroll
    for (int j = 0; j < 8; j++) {             // B: 2048 x 16B
        int idx = tid + j * THREADS;
        int n = idx >> 3, c = idx & 7;
        uint32_t dst = bB + (uint32_t)(n * ROWB + c * 16);
        const __half* src = Bg + (size_t)n * 512 + kc * BK + c * 8;
        asm volatile("cp.async.cg.shared.global [%0], [%1], 16;\n" ::"r"(dst), "l"(src));
    }
    asm volatile("cp.async.commit_group;\n");
}

// MMA over one staged chunk: 4 k16-steps; A and B frags both via ldmatrix.x4.
__device__ __forceinline__ void compute_chunk(uint32_t aAddr, uint32_t bAddr,
                                              float acc[4][8][4]) {
#pragma unroll
    for (int kk = 0; kk < 4; kk++) {
        uint32_t af[4][4], bf[4][4];
#pragma unroll
        for (int mt = 0; mt < 4; mt++)
            LDSM_X4(af[mt], aAddr + mt * (16 * ROWB) + kk * 32);
#pragma unroll
        for (int bt = 0; bt < 4; bt++)
            LDSM_X4(bf[bt], bAddr + bt * (16 * ROWB) + kk * 32);
#pragma unroll
        for (int mt = 0; mt < 4; mt++)
#pragma unroll
            for (int bt = 0; bt < 4; bt++) {
                mma16(acc[mt][2 * bt],     af[mt], bf[bt][0], bf[bt][2]);
                mma16(acc[mt][2 * bt + 1], af[mt], bf[bt][1], bf[bt][3]);
            }
    }
}

// One pass: acc[128x256] += A[128x512] @ B[256x512]^T (both K-major, fp16)
__device__ __forceinline__ void gemm_pass(const __half* __restrict__ Ag,
                                          const __half* __restrict__ Bg,
                                          uint32_t sAu, uint32_t sBu,
                                          uint32_t aAddr0, uint32_t bAddr0,
                                          int tid, float acc[4][8][4]) {
#pragma unroll
    for (int mt = 0; mt < 4; mt++)
#pragma unroll
        for (int nt = 0; nt < 8; nt++)
#pragma unroll
            for (int c = 0; c < 4; c++) acc[mt][nt][c] = 0.f;

    __syncthreads();  // prior pass fully done with all stages
    issue_chunk(Ag, Bg, 0, 0, tid, sAu, sBu);
    issue_chunk(Ag, Bg, 1, 1, tid, sAu, sBu);

    int stage = 0;  // stage of chunk kc == kc % STAGES
    for (int kc = 0; kc < NCHUNK; kc++) {
        if (kc + 1 < NCHUNK) {
            asm volatile("cp.async.wait_group 1;\n" ::);
        } else {
            asm volatile("cp.async.wait_group 0;\n" ::);
        }
        __syncthreads();  // chunk kc resident; all warps done with stage being refilled
        if (kc + 2 < NCHUNK) {
            int s2 = stage + 2;
            if (s2 >= STAGES) s2 -= STAGES;
            issue_chunk(Ag, Bg, kc + 2, s2, tid, sAu, sBu);
        }
        compute_chunk(aAddr0 + stage * ASTG, bAddr0 + stage * BSTG, acc);
        stage = (stage == STAGES - 1) ? 0 : stage + 1;
    }
}

__global__ void __launch_bounds__(THREADS, 1)
mlp_kernel(const float* __restrict__ b0, const float* __restrict__ b1,
           const float* __restrict__ W2, const float* __restrict__ b2,
           float* __restrict__ out) {
    extern __shared__ char smemc[];
    uint32_t sAu;
    asm("{ .reg .u64 t; cvta.to.shared.u64 t, %1; cvt.u32.u64 %0, t; }"
        : "=r"(sAu) : "l"(smemc));
    const uint32_t sBu = sAu + OFF_B;
    float* sLog = (float*)(smemc + OFF_LOG);  // 128 floats

    const int tid = threadIdx.x;
    const int warp = tid >> 5, lane = tid & 31;
    const int wm = warp >> 2, wn = warp & 3;  // 2 x 4 warp grid
    const int qid = lane >> 2, qt = lane & 3;
    const int p = blockIdx.y;
    const int gm0 = blockIdx.x * BM;

    // ldmatrix per-lane bases (stage 0, mt/bt = 0, kk = 0)
    const uint32_t aAddr0 =
        sAu + (uint32_t)((wm * 64 + (lane & 15)) * ROWB + ((lane & 16) ? 16 : 0));
    const uint32_t bAddr0 =
        sBu + (uint32_t)((wn * 64 + (lane & 15)) * ROWB + ((lane & 16) ? 16 : 0));

    const __half* Ax = (const __half*)g_xh + (size_t)gm0 * EE;
    __half* hb = (__half*)g_h0h + ((size_t)p * NN + gm0) * HH;

    float acc[4][8][4];

    // ---------------- Layer 0: h0 = fp16(relu(x @ W0[p] + b0[p])) ----------------
    for (int pass = 0; pass < 2; pass++) {
        const int n0 = pass * BN;
        gemm_pass(Ax, (const __half*)g_w0h + (size_t)p * EE * HH + (size_t)n0 * EE,
                  sAu, sBu, aAddr0, bAddr0, tid, acc);

        const float* bptr = b0 + p * HH + n0;
#pragma unroll
        for (int nt = 0; nt < 8; nt++) {
            int col = wn * 64 + nt * 8 + qt * 2;
            float2 bb = *(const float2*)(bptr + col);
#pragma unroll
            for (int mt = 0; mt < 4; mt++) {
                int row = wm * 64 + mt * 16 + qid;
                __half2 o0 = __floats2half2_rn(fmaxf(acc[mt][nt][0] + bb.x, 0.f),
                                               fmaxf(acc[mt][nt][1] + bb.y, 0.f));
                __half2 o1 = __floats2half2_rn(fmaxf(acc[mt][nt][2] + bb.x, 0.f),
                                               fmaxf(acc[mt][nt][3] + bb.y, 0.f));
                *(__half2*)(hb + (size_t)row * HH + n0 + col) = o0;
                *(__half2*)(hb + (size_t)(row + 8) * HH + n0 + col) = o1;
            }
        }
    }

    __threadfence();   // h0 visible in L2 before cp.async.cg reads it
    __syncthreads();
    if (tid < BM) sLog[tid] = 0.f;  // ordered before atomics by gemm_pass's syncs

    // ------- Layer 1 + 2 fused: logit[n] = sum_h relu(h1[n,h]) * W2[p,h] -------
    float lpart[8];
#pragma unroll
    for (int i = 0; i < 8; i++) lpart[i] = 0.f;

    for (int pass = 0; pass < 2; pass++) {
        const int n0 = pass * BN;
        gemm_pass(hb, (const __half*)g_w1h + (size_t)p * HH * HH + (size_t)n0 * HH,
                  sAu, sBu, aAddr0, bAddr0, tid, acc);

        const float* bptr = b1 + p * HH + n0;
        const float* wptr = W2 + p * HH + n0;
#pragma unroll
        for (int nt = 0; nt < 8; nt++) {
            int col = wn * 64 + nt * 8 + qt * 2;
            float2 bb = *(const float2*)(bptr + col);
            float2 ww = *(const float2*)(wptr + col);
#pragma unroll
            for (int mt = 0; mt < 4; mt++) {
                float v0 = fmaxf(acc[mt][nt][0] + bb.x, 0.f);
                float v1 = fmaxf(acc[mt][nt][1] + bb.y, 0.f);
                float v2 = fmaxf(acc[mt][nt][2] + bb.x, 0.f);
                float v3 = fmaxf(acc[mt][nt][3] + bb.y, 0.f);
                lpart[2 * mt]     += v0 * ww.x + v1 * ww.y;  // row qid
                lpart[2 * mt + 1] += v2 * ww.x + v3 * ww.y;  // row qid+8
            }
        }
    }

    // Reduce across qt lanes (quad), then smem atomics across warps/nt
#pragma unroll
    for (int i = 0; i < 8; i++) {
        float v = lpart[i];
        v += __shfl_xor_sync(0xffffffffu, v, 1);
        v += __shfl_xor_sync(0xffffffffu, v, 2);
        if (qt == 0) {
            int row = wm * 64 + (i >> 1) * 16 + ((i & 1) ? 8 : 0) + qid;
            atomicAdd(&sLog[row], v);
        }
    }
    __syncthreads();

    if (tid < BM) {
        float logit = sLog[tid] + b2[p];
        out[(size_t)(gm0 + tid) * PP + p] = 1.f / (1.f + expf(-logit));
    }
}

extern "C" void kernel_launch(void* const* d_in, const int* in_sizes, int n_in,
                              void* d_out, int out_size) {
    const float* x  = (const float*)d_in[0];
    const float* W0 = (const float*)d_in[1];
    const float* b0 = (const float*)d_in[2];
    const float* W1 = (const float*)d_in[3];
    const float* b1 = (const float*)d_in[4];
    const float* W2 = (const float*)d_in[5];
    const float* b2 = (const float*)d_in[6];
    float* out = (float*)d_out;

    // Prologue: fp16-convert x; transpose+convert W0, W1 (K-major B operands)
    cvt_x_kernel<<<(NN * EE / 8) / 256, 256>>>((const float4*)x);
    transpose_w_kernel<<<dim3(16, 16, 32), dim3(32, 8)>>>(W0, W1);

    cudaFuncSetAttribute(mlp_kernel, cudaFuncAttributeMaxDynamicSharedMemorySize,
                         SMEM_DYN);
    mlp_kernel<<<dim3(NN / BM, PP), THREADS, SMEM_DYN>>>(b0, b1, W2, b2, out);
}

// round 10
// speedup vs baseline: 2.0290x; 1.0130x over previous
#include <cuda_runtime.h>
#include <cuda_fp16.h>
#include <cstdint>

// Problem constants
#define PP 16
#define EE 512
#define HH 512
#define NN 8192

// Tiling: block tile 128x128, 4 warps (2x2), warp tile 64x64, fp16 K-chunk = 64
#define BM 128
#define BN 128
#define BK 64           // half elements per chunk (= 128B per row)
#define NCHUNK 8        // 512 / 64
#define NPASS 4         // 512 / BN
#define STAGES 3
#define THREADS 128

#define ROWB 144                 // padded row stride in bytes (128B data + 16B pad)
#define ASTG (128 * ROWB)        // 18432 B per A stage
#define BSTG (128 * ROWB)        // 18432 B per B stage
#define OFF_B (STAGES * ASTG)
#define OFF_LOG (STAGES * ASTG + STAGES * BSTG)   // 110592
#define SMEM_DYN (OFF_LOG + 512 + 16)

// Device scratch (uint4 => 16B aligned). All values stored as fp16 (RN).
__device__ uint4 g_xh[(size_t)NN * EE / 8];         // x          [N][E]   half
__device__ uint4 g_w0h[(size_t)PP * EE * HH / 8];   // W0^T       [P][H][E] half (K-major)
__device__ uint4 g_w1h[(size_t)PP * HH * HH / 8];   // W1^T       [P][Ho][Hi] half
__device__ uint4 g_h0h[(size_t)PP * NN * HH / 8];   // h0         [P][N][H] half

__device__ __forceinline__ uint32_t h2u(__half2 v) {
    uint32_t u;
    memcpy(&u, &v, 4);
    return u;
}

// ---------------- Prologue kernels ----------------

// x fp32 -> fp16, 8 elements/thread
__global__ void cvt_x_kernel(const float4* __restrict__ x) {
    int j = blockIdx.x * blockDim.x + threadIdx.x;
    if (j >= NN * EE / 8) return;
    float4 a = x[2 * j], b = x[2 * j + 1];
    uint4 o;
    o.x = h2u(__floats2half2_rn(a.x, a.y));
    o.y = h2u(__floats2half2_rn(a.z, a.w));
    o.z = h2u(__floats2half2_rn(b.x, b.y));
    o.w = h2u(__floats2half2_rn(b.z, b.w));
    g_xh[j] = o;
}

// Transpose + fp16-convert W0 [P,E,H]->[P,H,E] and W1 [P,H,H]->[P,Ho,Hi]
__global__ void transpose_w_kernel(const float* __restrict__ W0,
                                   const float* __restrict__ W1) {
    __shared__ float t[32][33];
    const int z = blockIdx.z;  // 0..15: W0 p=z ; 16..31: W1 p=z-16
    const float* src = (z < 16) ? W0 + (size_t)z * EE * HH
                                : W1 + (size_t)(z - 16) * HH * HH;
    __half* dst = (z < 16) ? (__half*)g_w0h + (size_t)z * EE * HH
                           : (__half*)g_w1h + (size_t)(z - 16) * HH * HH;
    const int c0 = blockIdx.x * 32;  // src col (output-neuron n) base
    const int r0 = blockIdx.y * 32;  // src row (input-dim k) base
    const int tx = threadIdx.x, ty = threadIdx.y;
#pragma unroll
    for (int i = ty; i < 32; i += 8)
        t[i][tx] = src[(size_t)(r0 + i) * 512 + c0 + tx];
    __syncthreads();
#pragma unroll
    for (int i = ty; i < 32; i += 8)
        dst[(size_t)(c0 + i) * 512 + r0 + tx] = __float2half_rn(t[tx][i]);
}

// ---------------- Main kernel ----------------

__device__ __forceinline__ void mma16(float c[4], const uint32_t a[4],
                                      uint32_t b0, uint32_t b1) {
    asm volatile(
        "mma.sync.aligned.m16n8k16.row.col.f32.f16.f16.f32 "
        "{%0,%1,%2,%3}, {%4,%5,%6,%7}, {%8,%9}, {%0,%1,%2,%3};\n"
        : "+f"(c[0]), "+f"(c[1]), "+f"(c[2]), "+f"(c[3])
        : "r"(a[0]), "r"(a[1]), "r"(a[2]), "r"(a[3]), "r"(b0), "r"(b1));
}

#define LDSM_X4(r, addr)                                                     \
    asm volatile("ldmatrix.sync.aligned.m8n8.x4.shared.b16 {%0,%1,%2,%3}, [%4];" \
                 : "=r"((r)[0]), "=r"((r)[1]), "=r"((r)[2]), "=r"((r)[3])    \
                 : "r"(addr))

// cp.async one K-chunk: A [128 rows x 128B] + B [128 rows x 128B] into a stage.
__device__ __forceinline__ void issue_chunk(const __half* __restrict__ Ag,
                                            const __half* __restrict__ Bg,
                                            int kc, int stage, int tid,
                                            uint32_t sAu, uint32_t sBu) {
    const uint32_t aB = sAu + stage * ASTG;
    const uint32_t bB = sBu + stage * BSTG;
#pragma unroll
    for (int j = 0; j < 8; j++) {             // A: 1024 x 16B over 128 threads
        int idx = tid + j * THREADS;
        int r = idx >> 3, c = idx & 7;
        uint32_t dst = aB + (uint32_t)(r * ROWB + c * 16);
        const __half* src = Ag + (size_t)r * 512 + kc * BK + c * 8;
        asm volatile("cp.async.cg.shared.global [%0], [%1], 16;\n" ::"r"(dst), "l"(src));
    }
#pragma unroll
    for (int j = 0; j < 8; j++) {             // B: 1024 x 16B
        int idx = tid + j * THREADS;
        int n = idx >> 3, c = idx & 7;
        uint32_t dst = bB + (uint32_t)(n * ROWB + c * 16);
        const __half* src = Bg + (size_t)n * 512 + kc * BK + c * 8;
        asm volatile("cp.async.cg.shared.global [%0], [%1], 16;\n" ::"r"(dst), "l"(src));
    }
    asm volatile("cp.async.commit_group;\n");
}

// MMA over one staged chunk: 4 k16-steps; A and B frags both via ldmatrix.x4.
__device__ __forceinline__ void compute_chunk(uint32_t aAddr, uint32_t bAddr,
                                              float acc[4][8][4]) {
#pragma unroll
    for (int kk = 0; kk < 4; kk++) {
        uint32_t af[4][4], bf[4][4];
#pragma unroll
        for (int mt = 0; mt < 4; mt++)
            LDSM_X4(af[mt], aAddr + mt * (16 * ROWB) + kk * 32);
#pragma unroll
        for (int bt = 0; bt < 4; bt++)
            LDSM_X4(bf[bt], bAddr + bt * (16 * ROWB) + kk * 32);
#pragma unroll
        for (int mt = 0; mt < 4; mt++)
#pragma unroll
            for (int bt = 0; bt < 4; bt++) {
                mma16(acc[mt][2 * bt],     af[mt], bf[bt][0], bf[bt][2]);
                mma16(acc[mt][2 * bt + 1], af[mt], bf[bt][1], bf[bt][3]);
            }
    }
}

// One pass: acc[128x128] += A[128x512] @ B[128x512]^T (both K-major, fp16)
__device__ __forceinline__ void gemm_pass(const __half* __restrict__ Ag,
                                          const __half* __restrict__ Bg,
                                          uint32_t sAu, uint32_t sBu,
                                          uint32_t aAddr0, uint32_t bAddr0,
                                          int tid, float acc[4][8][4]) {
#pragma unroll
    for (int mt = 0; mt < 4; mt++)
#pragma unroll
        for (int nt = 0; nt < 8; nt++)
#pragma unroll
            for (int c = 0; c < 4; c++) acc[mt][nt][c] = 0.f;

    __syncthreads();  // prior pass fully done with all stages
    issue_chunk(Ag, Bg, 0, 0, tid, sAu, sBu);
    issue_chunk(Ag, Bg, 1, 1, tid, sAu, sBu);

    int stage = 0;  // stage of chunk kc == kc % STAGES
    for (int kc = 0; kc < NCHUNK; kc++) {
        if (kc + 1 < NCHUNK) {
            asm volatile("cp.async.wait_group 1;\n" ::);
        } else {
            asm volatile("cp.async.wait_group 0;\n" ::);
        }
        __syncthreads();  // chunk kc resident; all warps done with stage being refilled
        if (kc + 2 < NCHUNK) {
            int s2 = stage + 2;
            if (s2 >= STAGES) s2 -= STAGES;
            issue_chunk(Ag, Bg, kc + 2, s2, tid, sAu, sBu);
        }
        compute_chunk(aAddr0 + stage * ASTG, bAddr0 + stage * BSTG, acc);
        stage = (stage == STAGES - 1) ? 0 : stage + 1;
    }
}

__global__ void __launch_bounds__(THREADS, 2)
mlp_kernel(const float* __restrict__ b0, const float* __restrict__ b1,
           const float* __restrict__ W2, const float* __restrict__ b2,
           float* __restrict__ out) {
    extern __shared__ char smemc[];
    uint32_t sAu;
    asm("{ .reg .u64 t; cvta.to.shared.u64 t, %1; cvt.u32.u64 %0, t; }"
        : "=r"(sAu) : "l"(smemc));
    const uint32_t sBu = sAu + OFF_B;
    float* sLog = (float*)(smemc + OFF_LOG);  // 128 floats

    const int tid = threadIdx.x;
    const int warp = tid >> 5, lane = tid & 31;
    const int wm = warp >> 1, wn = warp & 1;  // 2 x 2 warp grid
    const int qid = lane >> 2, qt = lane & 3;
    const int p = blockIdx.y;
    const int gm0 = blockIdx.x * BM;

    // ldmatrix per-lane bases (stage 0, mt/bt = 0, kk = 0)
    const uint32_t aAddr0 =
        sAu + (uint32_t)((wm * 64 + (lane & 15)) * ROWB + ((lane & 16) ? 16 : 0));
    const uint32_t bAddr0 =
        sBu + (uint32_t)((wn * 64 + (lane & 15)) * ROWB + ((lane & 16) ? 16 : 0));

    const __half* Ax = (const __half*)g_xh + (size_t)gm0 * EE;
    __half* hb = (__half*)g_h0h + ((size_t)p * NN + gm0) * HH;

    float acc[4][8][4];

    // ---------------- Layer 0: h0 = fp16(relu(x @ W0[p] + b0[p])) ----------------
    for (int pass = 0; pass < NPASS; pass++) {
        const int n0 = pass * BN;
        gemm_pass(Ax, (const __half*)g_w0h + (size_t)p * EE * HH + (size_t)n0 * EE,
                  sAu, sBu, aAddr0, bAddr0, tid, acc);

        const float* bptr = b0 + p * HH + n0;
#pragma unroll
        for (int nt = 0; nt < 8; nt++) {
            int col = wn * 64 + nt * 8 + qt * 2;
            float2 bb = *(const float2*)(bptr + col);
#pragma unroll
            for (int mt = 0; mt < 4; mt++) {
                int row = wm * 64 + mt * 16 + qid;
                __half2 o0 = __floats2half2_rn(fmaxf(acc[mt][nt][0] + bb.x, 0.f),
                                               fmaxf(acc[mt][nt][1] + bb.y, 0.f));
                __half2 o1 = __floats2half2_rn(fmaxf(acc[mt][nt][2] + bb.x, 0.f),
                                               fmaxf(acc[mt][nt][3] + bb.y, 0.f));
                *(__half2*)(hb + (size_t)row * HH + n0 + col) = o0;
                *(__half2*)(hb + (size_t)(row + 8) * HH + n0 + col) = o1;
            }
        }
    }

    __threadfence();   // h0 visible in L2 before cp.async.cg reads it
    __syncthreads();
    if (tid < BM) sLog[tid] = 0.f;  // ordered before atomics by gemm_pass's syncs

    // ------- Layer 1 + 2 fused: logit[n] = sum_h relu(h1[n,h]) * W2[p,h] -------
    float lpart[8];
#pragma unroll
    for (int i = 0; i < 8; i++) lpart[i] = 0.f;

    for (int pass = 0; pass < NPASS; pass++) {
        const int n0 = pass * BN;
        gemm_pass(hb, (const __half*)g_w1h + (size_t)p * HH * HH + (size_t)n0 * HH,
                  sAu, sBu, aAddr0, bAddr0, tid, acc);

        const float* bptr = b1 + p * HH + n0;
        const float* wptr = W2 + p * HH + n0;
#pragma unroll
        for (int nt = 0; nt < 8; nt++) {
            int col = wn * 64 + nt * 8 + qt * 2;
            float2 bb = *(const float2*)(bptr + col);
            float2 ww = *(const float2*)(wptr + col);
#pragma unroll
            for (int mt = 0; mt < 4; mt++) {
                float v0 = fmaxf(acc[mt][nt][0] + bb.x, 0.f);
                float v1 = fmaxf(acc[mt][nt][1] + bb.y, 0.f);
                float v2 = fmaxf(acc[mt][nt][2] + bb.x, 0.f);
                float v3 = fmaxf(acc[mt][nt][3] + bb.y, 0.f);
                lpart[2 * mt]     += v0 * ww.x + v1 * ww.y;  // row qid
                lpart[2 * mt + 1] += v2 * ww.x + v3 * ww.y;  // row qid+8
            }
        }
    }

    // Reduce across qt lanes (quad), then smem atomics across warps/nt
#pragma unroll
    for (int i = 0; i < 8; i++) {
        float v = lpart[i];
        v += __shfl_xor_sync(0xffffffffu, v, 1);
        v += __shfl_xor_sync(0xffffffffu, v, 2);
        if (qt == 0) {
            int row = wm * 64 + (i >> 1) * 16 + ((i & 1) ? 8 : 0) + qid;
            atomicAdd(&sLog[row], v);
        }
    }
    __syncthreads();

    if (tid < BM) {
        float logit = sLog[tid] + b2[p];
        out[(size_t)(gm0 + tid) * PP + p] = 1.f / (1.f + expf(-logit));
    }
}

extern "C" void kernel_launch(void* const* d_in, const int* in_sizes, int n_in,
                              void* d_out, int out_size) {
    const float* x  = (const float*)d_in[0];
    const float* W0 = (const float*)d_in[1];
    const float* b0 = (const float*)d_in[2];
    const float* W1 = (const float*)d_in[3];
    const float* b1 = (const float*)d_in[4];
    const float* W2 = (const float*)d_in[5];
    const float* b2 = (const float*)d_in[6];
    float* out = (float*)d_out;

    // Prologue: fp16-convert x; transpose+convert W0, W1 (K-major B operands)
    cvt_x_kernel<<<(NN * EE / 8) / 256, 256>>>((const float4*)x);
    transpose_w_kernel<<<dim3(16, 16, 32), dim3(32, 8)>>>(W0, W1);

    cudaFuncSetAttribute(mlp_kernel, cudaFuncAttributeMaxDynamicSharedMemorySize,
                         SMEM_DYN);
    mlp_kernel<<<dim3(NN / BM, PP), THREADS, SMEM_DYN>>>(b0, b1, W2, b2, out);
}